// round 10
// baseline (speedup 1.0000x reference)
#include <cuda_runtime.h>
#include <math.h>

#define BB 8
#define CC 64
#define NN 4096
#define KK 32
#define NPTS (BB*NN)          // 32768
#define EPSB 1e-5f
#define NEG_INF (-3.4e38f)
#define FULLM 0xffffffffu

// ---------------- device scratch (static, allocation-free) ----------------
__device__ float g_Pq[NPTS*CC];
__device__ float g_Pk[NPTS*CC];
__device__ float g_Pv[NPTS*CC];
__device__ float g_sq[NPTS];
__device__ int   g_idx[NPTS*KK];
__device__ float g_y1[(size_t)NPTS*CC];
__device__ float g_y2[(size_t)NPTS*CC];
__device__ float g_stats[256];               // [sum1|sumsq1|sum2|sumsq2] x 64ch

// ---------------- zero stats (graph-replay safe; also used as pad launch) ----------------
__global__ void k_zero() { g_stats[threadIdx.x] = 0.f; }

// ---------------- K1: feat projections Pq/Pk/Pv + sq ----------------
__global__ void k_proj(const float* __restrict__ x, const float* __restrict__ wq,
                       const float* __restrict__ wk, const float* __restrict__ wv) {
    extern __shared__ float sm[];
    float* sW = sm;              // 3 * 64*65, layout [w][c*65+o] (transposed, padded)
    float* sf = sm + 3*4160;     // 64*65, layout [p*65+c]
    int t = threadIdx.x;
    int b  = blockIdx.x >> 6;
    int n0 = (blockIdx.x & 63) * 64;
    const float* ws[3] = {wq, wk, wv};
#pragma unroll
    for (int w = 0; w < 3; w++)
#pragma unroll
        for (int s = 0; s < 16; s++) {
            int i = t + 256*s; int o = i >> 6, c = i & 63;
            sW[w*4160 + c*65 + o] = ws[w][i];
        }
    const float* xb = x + (size_t)b*CC*NN;
#pragma unroll
    for (int s = 0; s < 16; s++) {
        int i = t + 256*s; int c = i >> 6, p = i & 63;
        sf[p*65 + c] = xb[c*NN + n0 + p];
    }
    __syncthreads();
    if (t < 64) {
        float s = 0.f;
#pragma unroll
        for (int c = 0; c < 64; c++) { float v = sf[t*65+c]; s += v*v; }
        g_sq[b*NN + n0 + t] = s;
    }
    float* outs[3] = {g_Pq, g_Pk, g_Pv};
#pragma unroll
    for (int w = 0; w < 3; w++)
#pragma unroll
        for (int s = 0; s < 16; s++) {
            int i = t + 256*s; int p = i >> 6, o = i & 63;
            float acc = 0.f;
#pragma unroll
            for (int c = 0; c < 64; c++)
                acc += sf[p*65+c] * sW[w*4160 + c*65 + o];
            outs[w][(size_t)(b*NN + n0 + p)*CC + o] = acc;
        }
}

// ---------------- K2: FUSED distance GEMM + streaming top-32 (v3) ----------------
// 128x128 tiles, 256 threads (16x16), 8x8 micro-tile (LDS/FMA balanced).
// Scores scanned DIRECTLY from registers (no score smem): warp w's lanes hold
// rows 16w..16w+15; lanes 0-15 own rows 16w+i (acc row i), lanes 16-31 own
// rows 16w+8+i. Per-row: fold 2*acc - sq[m], per-lane 8-col max, one warp
// ballot vs the running 32nd-best threshold; rare passes feed a sorted
// register-resident top-32 list (1 entry/lane, shfl insert). Strictly-greater
// admission + ascending-column processing matches top_k tie semantics.
__global__ void __launch_bounds__(256, 2)
k_dist_topk(const float* __restrict__ x) {
    extern __shared__ float sm[];
    float* As  = sm;                 // [k*132 + r]  64 x 128 (+pad)
    float* Bs  = sm + 64*132;        // [k*132 + m]  64 x 128 (+pad)
    float* sqs = Bs + 64*132;        // [128]
    int t  = threadIdx.x;
    int b  = blockIdx.y;
    int n0 = blockIdx.x * 128;
    const float* xb = x + (size_t)b*CC*NN;

    int tx = t & 15, ty = t >> 4;
    int lane = t & 31, w = t >> 5;

    // load A tile (128 rows x 64 ch), layout [k][r], float4
#pragma unroll
    for (int s = 0; s < 8; s++) {
        int i4 = (s*256 + t) * 4; int c = i4 >> 7, r = i4 & 127;
        *(float4*)(As + c*132 + r) = *(const float4*)(xb + c*NN + n0 + r);
    }

    float Lv[16]; unsigned Lipk[8];
#pragma unroll
    for (int r = 0; r < 16; r++) Lv[r] = NEG_INF;
#pragma unroll
    for (int i = 0; i < 8; i++) Lipk[i] = 0u;

    for (int tile = 0; tile < 32; tile++) {
        int m0 = tile * 128;
        float sqld = (t < 128) ? g_sq[b*NN + m0 + t] : 0.f;   // overlap with B load
        __syncthreads();
#pragma unroll
        for (int s = 0; s < 8; s++) {
            int i4 = (s*256 + t) * 4; int c = i4 >> 7, m = i4 & 127;
            *(float4*)(Bs + c*132 + m) = *(const float4*)(xb + c*NN + m0 + m);
        }
        if (t < 128) sqs[t] = sqld;
        __syncthreads();

        // GEMM: rows ty*8..+7, cols tx*8..+7
        float acc[8][8];
#pragma unroll
        for (int i = 0; i < 8; i++)
#pragma unroll
            for (int j = 0; j < 8; j++) acc[i][j] = 0.f;
#pragma unroll 4
        for (int k = 0; k < 64; k++) {
            float4 a0 = *(const float4*)(As + k*132 + ty*8);
            float4 a1 = *(const float4*)(As + k*132 + ty*8 + 4);
            float4 b0 = *(const float4*)(Bs + k*132 + tx*8);
            float4 b1 = *(const float4*)(Bs + k*132 + tx*8 + 4);
            float av[8] = {a0.x,a0.y,a0.z,a0.w,a1.x,a1.y,a1.z,a1.w};
            float bv[8] = {b0.x,b0.y,b0.z,b0.w,b1.x,b1.y,b1.z,b1.w};
#pragma unroll
            for (int i = 0; i < 8; i++)
#pragma unroll
                for (int j = 0; j < 8; j++) acc[i][j] += av[i]*bv[j];
        }

        // fold score = 2*acc - sq[m]; per-acc-row max
        float4 sq0 = *(const float4*)(sqs + tx*8);
        float4 sq1 = *(const float4*)(sqs + tx*8 + 4);
        float sqv[8] = {sq0.x,sq0.y,sq0.z,sq0.w,sq1.x,sq1.y,sq1.z,sq1.w};
        float rowmax[8];
#pragma unroll
        for (int i = 0; i < 8; i++) {
            float mx = NEG_INF;
#pragma unroll
            for (int j = 0; j < 8; j++) {
                acc[i][j] = fmaf(2.f, acc[i][j], -sqv[j]);
                mx = fmaxf(mx, acc[i][j]);
            }
            rowmax[i] = mx;
        }

        // register scan: 16 rows per warp
#pragma unroll
        for (int r16 = 0; r16 < 16; r16++) {
            const int i = r16 & 7;
            const bool hi = r16 >= 8;
            bool owner = ((lane < 16) == (r16 < 8));
            float thr = __shfl_sync(FULLM, Lv[r16], 31);
            float lm = owner ? rowmax[i] : NEG_INF;
            unsigned pmask = __ballot_sync(FULLM, lm > thr);
            while (pmask) {
                int src = __ffs(pmask) - 1; pmask &= pmask - 1;
                int scol = m0 + ((src & 15) << 3);
#pragma unroll
                for (int j = 0; j < 8; j++) {
                    float vv = __shfl_sync(FULLM, acc[i][j], src);
                    if (vv > thr) {   // warp-uniform (vv, thr broadcast)
                        int vi = scol + j;
                        int pos = __popc(__ballot_sync(FULLM, Lv[r16] >= vv));
                        float sv = __shfl_up_sync(FULLM, Lv[r16], 1);
                        unsigned sp = __shfl_up_sync(FULLM, Lipk[i], 1);
                        if (lane > pos) {
                            Lv[r16] = sv;
                            Lipk[i] = hi ? ((Lipk[i] & 0xFFFFu) | (sp & 0xFFFF0000u))
                                         : ((Lipk[i] & 0xFFFF0000u) | (sp & 0xFFFFu));
                        } else if (lane == pos) {
                            Lv[r16] = vv;
                            Lipk[i] = hi ? ((Lipk[i] & 0xFFFFu) | ((unsigned)vi << 16))
                                         : ((Lipk[i] & 0xFFFF0000u) | (unsigned)vi);
                        }
                        thr = __shfl_sync(FULLM, Lv[r16], 31);
                    }
                }
            }
        }
    }
    // emit: lane l = rank l of each owned row
#pragma unroll
    for (int r16 = 0; r16 < 16; r16++) {
        const int i = r16 & 7;
        int idx = (r16 >= 8) ? (int)(Lipk[i] >> 16) : (int)(Lipk[i] & 0xFFFFu);
        int row = b*NN + n0 + w*16 + r16;
        g_idx[(size_t)row*KK + lane] = idx;
    }
}

// ---------------- K4: attention via gathered projections + residual + BN1 stats ----------------
__global__ void k_attn(const float* __restrict__ x) {
    __shared__ int   sidx[2][32];
    __shared__ float sred[128];
    int t  = threadIdx.x;
    int pt = t >> 6;
    int c  = t & 63;
    int P  = blockIdx.x*2 + pt;        // global row = b*4096 + n
    int b  = P >> 12;
    int n  = P & 4095;
    if (c < 32) sidx[pt][c] = g_idx[(size_t)P*KK + c];
    __syncthreads();
    size_t rb = (size_t)P*CC;
    float qc  = g_Pq[rb + c];
    float pkn = g_Pk[rb + c];
    float pvn = g_Pv[rb + c];
    size_t bbase = (size_t)b << 12;
    float e[32];
#pragma unroll
    for (int j = 0; j < 32; j++) {
        int m = sidx[pt][j];
        float p = qc * (g_Pk[(bbase + m)*CC + c] - pkn);
        p += __shfl_xor_sync(FULLM, p, 8);
        p += __shfl_xor_sync(FULLM, p, 4);
        p += __shfl_xor_sync(FULLM, p, 2);
        p += __shfl_xor_sync(FULLM, p, 1);
        e[j] = p * 0.25f;                     // / sqrt(D), D=16
    }
    float mx = e[0];
#pragma unroll
    for (int j=1;j<32;j++) mx = fmaxf(mx, e[j]);
    float ssum = 0.f;
#pragma unroll
    for (int j=0;j<32;j++){ e[j] = __expf(e[j]-mx); ssum += e[j]; }
    float inv = 1.f/ssum;
    float acc = 0.f;
#pragma unroll
    for (int j=0;j<32;j++){
        int m = sidx[pt][j];
        acc += e[j] * g_Pv[(bbase + m)*CC + c];
    }
    float outv = acc*inv - pvn;
    float y = x[(size_t)b*CC*NN + (size_t)c*NN + n] + outv;
    g_y1[rb + c] = y;
    sred[t] = y; __syncthreads();
    if (t < 64) atomicAdd(&g_stats[c], sred[t] + sred[t+64]);
    __syncthreads();
    sred[t] = y*y; __syncthreads();
    if (t < 64) atomicAdd(&g_stats[64+c], sred[t] + sred[t+64]);
}

// ---------------- K6: BN1 apply + MLP (fused, weights resident) + BN2 stats ----------------
__global__ void __launch_bounds__(256, 1)
k_mlp(const float* __restrict__ w1, const float* __restrict__ w2,
      const float* __restrict__ g1, const float* __restrict__ b1) {
    extern __shared__ float sm[];
    float* sW1  = sm;                      // [c*257+o]
    float* sW2  = sm + 16448;              // [c*257+o]
    float* sf1  = sm + 2*16448;            // [p*65+c]
    float* shid = sm + 2*16448 + 2080;     // [p*256+o]
    __shared__ float sred[256];
    int t = threadIdx.x;
    int rowbase = blockIdx.x * 32;
#pragma unroll
    for (int s = 0; s < 64; s++) {
        int i = t + 256*s; int o = i >> 6, c = i & 63;
        sW1[c*257 + o] = w1[i];
    }
#pragma unroll
    for (int s = 0; s < 64; s++) {
        int i = t + 256*s; int c = i >> 8, o = i & 255;
        sW2[c*257 + o] = w2[i];
    }
    const float invN = 1.f/32768.f;
#pragma unroll
    for (int s = 0; s < 8; s++) {
        int i = t + 256*s; int p = i >> 6, c = i & 63;
        float mu  = g_stats[c]*invN;
        float var = g_stats[64+c]*invN - mu*mu;
        float v = g_y1[(size_t)(rowbase+p)*CC + c];
        sf1[p*65 + c] = (v - mu)*rsqrtf(var + EPSB)*g1[c] + b1[c];
    }
    __syncthreads();
    {
        int o = t;
#pragma unroll
        for (int pb = 0; pb < 4; pb++) {
            float acc[8];
#pragma unroll
            for (int p=0;p<8;p++) acc[p]=0.f;
#pragma unroll
            for (int cc2 = 0; cc2 < 64; cc2++) {
                float w = sW1[cc2*257 + o];
#pragma unroll
                for (int p=0;p<8;p++) acc[p] += sf1[(pb*8+p)*65 + cc2]*w;
            }
#pragma unroll
            for (int p=0;p<8;p++){
                float h = acc[p];
                shid[(pb*8+p)*256 + o] = h > 0.f ? h : 0.2f*h;
            }
        }
    }
    __syncthreads();
    {
        int c = t & 63; int pg = t >> 6;
        float acc[8];
#pragma unroll
        for (int q=0;q<8;q++) acc[q]=0.f;
#pragma unroll 16
        for (int oo = 0; oo < 256; oo++) {
            float w = sW2[c*257 + oo];
#pragma unroll
            for (int q=0;q<8;q++) acc[q] += shid[(pg*8+q)*256 + oo]*w;
        }
        float psum=0.f, psq=0.f;
#pragma unroll
        for (int q=0;q<8;q++){
            int p = pg*8+q;
            float y = sf1[p*65 + c] + acc[q];
            g_y2[(size_t)(rowbase+p)*CC + c] = y;
            psum += y; psq += y*y;
        }
        sred[t]=psum; __syncthreads();
        if (t<64){
            float s2=sred[t]+sred[t+64]+sred[t+128]+sred[t+192];
            atomicAdd(&g_stats[128+t], s2);
        }
        __syncthreads();
        sred[t]=psq; __syncthreads();
        if (t<64){
            float s2=sred[t]+sred[t+64]+sred[t+128]+sred[t+192];
            atomicAdd(&g_stats[192+t], s2);
        }
    }
}

// ---------------- K7: BN2 apply + transpose to (B,C,N) ----------------
__global__ void k_final(float* __restrict__ out, const float* __restrict__ g2,
                        const float* __restrict__ b2) {
    __shared__ float tile[64*65];
    int t = threadIdx.x;
    int b  = blockIdx.x >> 6;
    int n0 = (blockIdx.x & 63)*64;
    const float invN = 1.f/32768.f;
#pragma unroll
    for (int s = 0; s < 16; s++) {
        int i = t + 256*s; int p = i >> 6, c = i & 63;
        float mu  = g_stats[128+c]*invN;
        float var = g_stats[192+c]*invN - mu*mu;
        float v = g_y2[(size_t)(b*NN + n0 + p)*CC + c];
        tile[c*65 + p] = (v-mu)*rsqrtf(var+EPSB)*g2[c] + b2[c];
    }
    __syncthreads();
#pragma unroll
    for (int s = 0; s < 16; s++) {
        int i = t + 256*s; int c = i >> 6, p = i & 63;
        out[(size_t)b*CC*NN + (size_t)c*NN + n0 + p] = tile[c*65 + p];
    }
}

// ---------------- launch ----------------
extern "C" void kernel_launch(void* const* d_in, const int* in_sizes, int n_in,
                              void* d_out, int out_size) {
    const float* x  = (const float*)d_in[0];
    const float* wq = (const float*)d_in[1];
    const float* wk = (const float*)d_in[2];
    const float* wv = (const float*)d_in[3];
    const float* w1 = (const float*)d_in[4];
    const float* w2 = (const float*)d_in[5];
    const float* g1 = (const float*)d_in[6];
    const float* b1 = (const float*)d_in[7];
    const float* g2 = (const float*)d_in[8];
    const float* b2 = (const float*)d_in[9];
    float* out = (float*)d_out;

    const int PROJ_SMEM = 4*4160*4;                  // 66560
    const int DT_SMEM   = (2*64*132 + 128)*4;        // 68096
    const int MLP_SMEM  = (2*16448 + 2080 + 32*256)*4;   // 172672
    cudaFuncSetAttribute(k_proj,      cudaFuncAttributeMaxDynamicSharedMemorySize, PROJ_SMEM);
    cudaFuncSetAttribute(k_dist_topk, cudaFuncAttributeMaxDynamicSharedMemorySize, DT_SMEM);
    cudaFuncSetAttribute(k_mlp,       cudaFuncAttributeMaxDynamicSharedMemorySize, MLP_SMEM);

    k_zero<<<1, 256>>>();                             // launch 1
    k_proj<<<512, 256, PROJ_SMEM>>>(x, wq, wk, wv);   // launch 2
    k_zero<<<1, 256>>>();                             // launch 3 (pad for ncu)
    k_dist_topk<<<dim3(32, 8), 256, DT_SMEM>>>(x);    // launch 4 -> profiled
    k_attn<<<NPTS/2, 128>>>(x);
    k_mlp<<<NPTS/32, 256, MLP_SMEM>>>(w1, w2, g1, b1);
    k_final<<<512, 256>>>(out, g2, b2);
}

// round 13
// speedup vs baseline: 2.0102x; 2.0102x over previous
#include <cuda_runtime.h>
#include <math.h>

#define BB 8
#define CC 64
#define NN 4096
#define KK 32
#define NPTS (BB*NN)          // 32768
#define EPSB 1e-5f
#define NEG_INF (-3.4e38f)
#define FULLM 0xffffffffu

// ---------------- device scratch (static, allocation-free) ----------------
__device__ float g_Pq[NPTS*CC];
__device__ float g_Pk[NPTS*CC];
__device__ float g_Pv[NPTS*CC];
__device__ float g_sq[NPTS];
__device__ int   g_idx[NPTS*KK];
__device__ float g_y1[(size_t)NPTS*CC];
__device__ float g_y2[(size_t)NPTS*CC];
__device__ float g_stats[256];               // [sum1|sumsq1|sum2|sumsq2] x 64ch

// ---------------- zero stats (graph-replay safe; also used as pad launch) ----------------
__global__ void k_zero() { g_stats[threadIdx.x] = 0.f; }

// ---------------- K1: feat projections Pq/Pk/Pv + sq ----------------
__global__ void k_proj(const float* __restrict__ x, const float* __restrict__ wq,
                       const float* __restrict__ wk, const float* __restrict__ wv) {
    extern __shared__ float sm[];
    float* sW = sm;              // 3 * 64*65, layout [w][c*65+o] (transposed, padded)
    float* sf = sm + 3*4160;     // 64*65, layout [p*65+c]
    int t = threadIdx.x;
    int b  = blockIdx.x >> 6;
    int n0 = (blockIdx.x & 63) * 64;
    const float* ws[3] = {wq, wk, wv};
#pragma unroll
    for (int w = 0; w < 3; w++)
#pragma unroll
        for (int s = 0; s < 16; s++) {
            int i = t + 256*s; int o = i >> 6, c = i & 63;
            sW[w*4160 + c*65 + o] = ws[w][i];
        }
    const float* xb = x + (size_t)b*CC*NN;
#pragma unroll
    for (int s = 0; s < 16; s++) {
        int i = t + 256*s; int c = i >> 6, p = i & 63;
        sf[p*65 + c] = xb[c*NN + n0 + p];
    }
    __syncthreads();
    if (t < 64) {
        float s = 0.f;
#pragma unroll
        for (int c = 0; c < 64; c++) { float v = sf[t*65+c]; s += v*v; }
        g_sq[b*NN + n0 + t] = s;
    }
    float* outs[3] = {g_Pq, g_Pk, g_Pv};
#pragma unroll
    for (int w = 0; w < 3; w++)
#pragma unroll
        for (int s = 0; s < 16; s++) {
            int i = t + 256*s; int p = i >> 6, o = i & 63;
            float acc = 0.f;
#pragma unroll
            for (int c = 0; c < 64; c++)
                acc += sf[p*65+c] * sW[w*4160 + c*65 + o];
            outs[w][(size_t)(b*NN + n0 + p)*CC + o] = acc;
        }
}

// ---------------- K2: FUSED distance GEMM + streaming top-32 (v4) ----------------
// 128x128 tiles, 256 threads (16x16), 8x8 micro-tile (LDS/FMA balanced).
// v4: persistent top-32 lists live in SHARED memory (sLv/sLi, 128 rows x 32
// lanes) instead of registers -> peak reg demand ~95 (no spills at the 128
// cap that wrecked v3). Per tile each row's list is pulled into 2 regs/lane,
// ballot-scanned against the accumulator registers, stored back only if an
// insert occurred. Strictly-greater admission + ascending-column order
// matches top_k tie semantics (set equality; softmax is permutation-inv).
__global__ void __launch_bounds__(256, 2)
k_dist_topk(const float* __restrict__ x) {
    extern __shared__ float sm[];
    float* As  = sm;                    // [k*132 + r]  64 x 128 (+pad)
    float* Bs  = sm + 64*132;           // [k*132 + m]  64 x 128 (+pad)
    float* sqs = Bs + 64*132;           // [128]
    float* sLv = sqs + 128;             // [128 rows][32 lanes]
    int*   sLi = (int*)(sLv + 128*32);  // [128 rows][32 lanes]
    int t  = threadIdx.x;
    int b  = blockIdx.y;
    int n0 = blockIdx.x * 128;
    const float* xb = x + (size_t)b*CC*NN;

    int tx = t & 15, ty = t >> 4;
    int lane = t & 31, w = t >> 5;

    // init lists
#pragma unroll
    for (int s = 0; s < 16; s++) { sLv[s*256 + t] = NEG_INF; sLi[s*256 + t] = 0; }

    // load A tile (128 rows x 64 ch), layout [k][r], float4
#pragma unroll
    for (int s = 0; s < 8; s++) {
        int i4 = (s*256 + t) * 4; int c = i4 >> 7, r = i4 & 127;
        *(float4*)(As + c*132 + r) = *(const float4*)(xb + c*NN + n0 + r);
    }

    for (int tile = 0; tile < 32; tile++) {
        int m0 = tile * 128;
        float sqld = (t < 128) ? g_sq[b*NN + m0 + t] : 0.f;   // overlap with B load
        __syncthreads();
#pragma unroll
        for (int s = 0; s < 8; s++) {
            int i4 = (s*256 + t) * 4; int c = i4 >> 7, m = i4 & 127;
            *(float4*)(Bs + c*132 + m) = *(const float4*)(xb + c*NN + m0 + m);
        }
        if (t < 128) sqs[t] = sqld;
        __syncthreads();

        // GEMM: rows ty*8..+7, cols tx*8..+7
        float acc[8][8];
#pragma unroll
        for (int i = 0; i < 8; i++)
#pragma unroll
            for (int j = 0; j < 8; j++) acc[i][j] = 0.f;
#pragma unroll 4
        for (int k = 0; k < 64; k++) {
            float4 a0 = *(const float4*)(As + k*132 + ty*8);
            float4 a1 = *(const float4*)(As + k*132 + ty*8 + 4);
            float4 b0 = *(const float4*)(Bs + k*132 + tx*8);
            float4 b1 = *(const float4*)(Bs + k*132 + tx*8 + 4);
            float av[8] = {a0.x,a0.y,a0.z,a0.w,a1.x,a1.y,a1.z,a1.w};
            float bv[8] = {b0.x,b0.y,b0.z,b0.w,b1.x,b1.y,b1.z,b1.w};
#pragma unroll
            for (int i = 0; i < 8; i++)
#pragma unroll
                for (int j = 0; j < 8; j++) acc[i][j] += av[i]*bv[j];
        }

        // fold score = 2*acc - sq[m]; per-acc-row max
        float4 sq0 = *(const float4*)(sqs + tx*8);
        float4 sq1 = *(const float4*)(sqs + tx*8 + 4);
        float sqv[8] = {sq0.x,sq0.y,sq0.z,sq0.w,sq1.x,sq1.y,sq1.z,sq1.w};
        float rowmax[8];
#pragma unroll
        for (int i = 0; i < 8; i++) {
            float mx = NEG_INF;
#pragma unroll
            for (int j = 0; j < 8; j++) {
                acc[i][j] = fmaf(2.f, acc[i][j], -sqv[j]);
                mx = fmaxf(mx, acc[i][j]);
            }
            rowmax[i] = mx;
        }

        // register scan over 16 rows per warp; lists staged from smem
#pragma unroll
        for (int r16 = 0; r16 < 16; r16++) {
            const int i = r16 & 7;
            bool owner = ((lane < 16) == (r16 < 8));
            int rl = w*16 + r16;
            float lv = sLv[rl*32 + lane];
            float thr = __shfl_sync(FULLM, lv, 31);
            unsigned pmask = __ballot_sync(FULLM, (owner ? rowmax[i] : NEG_INF) > thr);
            if (pmask) {
                int li = sLi[rl*32 + lane];
                do {
                    int src = __ffs(pmask) - 1; pmask &= pmask - 1;
                    int scol = m0 + ((src & 15) << 3);
#pragma unroll
                    for (int j = 0; j < 8; j++) {
                        float vv = __shfl_sync(FULLM, acc[i][j], src);
                        if (vv > thr) {   // warp-uniform (vv, thr broadcast)
                            int vi = scol + j;
                            int pos = __popc(__ballot_sync(FULLM, lv >= vv));
                            float sv = __shfl_up_sync(FULLM, lv, 1);
                            int   si = __shfl_up_sync(FULLM, li, 1);
                            if (lane > pos)       { lv = sv; li = si; }
                            else if (lane == pos) { lv = vv; li = vi; }
                            thr = __shfl_sync(FULLM, lv, 31);
                        }
                    }
                } while (pmask);
                sLv[rl*32 + lane] = lv;
                sLi[rl*32 + lane] = li;
            }
        }
    }
    __syncthreads();
    // emit: lane l = rank l of each owned row
#pragma unroll
    for (int r16 = 0; r16 < 16; r16++) {
        int rl = w*16 + r16;
        int row = b*NN + n0 + rl;
        g_idx[(size_t)row*KK + lane] = sLi[rl*32 + lane];
    }
}

// ---------------- K4: attention via gathered projections + residual + BN1 stats ----------------
__global__ void k_attn(const float* __restrict__ x) {
    __shared__ int   sidx[2][32];
    __shared__ float sred[128];
    int t  = threadIdx.x;
    int pt = t >> 6;
    int c  = t & 63;
    int P  = blockIdx.x*2 + pt;        // global row = b*4096 + n
    int b  = P >> 12;
    int n  = P & 4095;
    if (c < 32) sidx[pt][c] = g_idx[(size_t)P*KK + c];
    __syncthreads();
    size_t rb = (size_t)P*CC;
    float qc  = g_Pq[rb + c];
    float pkn = g_Pk[rb + c];
    float pvn = g_Pv[rb + c];
    size_t bbase = (size_t)b << 12;
    float e[32];
#pragma unroll
    for (int j = 0; j < 32; j++) {
        int m = sidx[pt][j];
        float p = qc * (g_Pk[(bbase + m)*CC + c] - pkn);
        p += __shfl_xor_sync(FULLM, p, 8);
        p += __shfl_xor_sync(FULLM, p, 4);
        p += __shfl_xor_sync(FULLM, p, 2);
        p += __shfl_xor_sync(FULLM, p, 1);
        e[j] = p * 0.25f;                     // / sqrt(D), D=16
    }
    float mx = e[0];
#pragma unroll
    for (int j=1;j<32;j++) mx = fmaxf(mx, e[j]);
    float ssum = 0.f;
#pragma unroll
    for (int j=0;j<32;j++){ e[j] = __expf(e[j]-mx); ssum += e[j]; }
    float inv = 1.f/ssum;
    float acc = 0.f;
#pragma unroll
    for (int j=0;j<32;j++){
        int m = sidx[pt][j];
        acc += e[j] * g_Pv[(bbase + m)*CC + c];
    }
    float outv = acc*inv - pvn;
    float y = x[(size_t)b*CC*NN + (size_t)c*NN + n] + outv;
    g_y1[rb + c] = y;
    sred[t] = y; __syncthreads();
    if (t < 64) atomicAdd(&g_stats[c], sred[t] + sred[t+64]);
    __syncthreads();
    sred[t] = y*y; __syncthreads();
    if (t < 64) atomicAdd(&g_stats[64+c], sred[t] + sred[t+64]);
}

// ---------------- K6: BN1 apply + MLP (fused, weights resident) + BN2 stats ----------------
__global__ void __launch_bounds__(256, 1)
k_mlp(const float* __restrict__ w1, const float* __restrict__ w2,
      const float* __restrict__ g1, const float* __restrict__ b1) {
    extern __shared__ float sm[];
    float* sW1  = sm;                      // [c*257+o]
    float* sW2  = sm + 16448;              // [c*257+o]
    float* sf1  = sm + 2*16448;            // [p*65+c]
    float* shid = sm + 2*16448 + 2080;     // [p*256+o]
    __shared__ float sred[256];
    int t = threadIdx.x;
    int rowbase = blockIdx.x * 32;
#pragma unroll
    for (int s = 0; s < 64; s++) {
        int i = t + 256*s; int o = i >> 6, c = i & 63;
        sW1[c*257 + o] = w1[i];
    }
#pragma unroll
    for (int s = 0; s < 64; s++) {
        int i = t + 256*s; int c = i >> 8, o = i & 255;
        sW2[c*257 + o] = w2[i];
    }
    const float invN = 1.f/32768.f;
#pragma unroll
    for (int s = 0; s < 8; s++) {
        int i = t + 256*s; int p = i >> 6, c = i & 63;
        float mu  = g_stats[c]*invN;
        float var = g_stats[64+c]*invN - mu*mu;
        float v = g_y1[(size_t)(rowbase+p)*CC + c];
        sf1[p*65 + c] = (v - mu)*rsqrtf(var + EPSB)*g1[c] + b1[c];
    }
    __syncthreads();
    {
        int o = t;
#pragma unroll
        for (int pb = 0; pb < 4; pb++) {
            float acc[8];
#pragma unroll
            for (int p=0;p<8;p++) acc[p]=0.f;
#pragma unroll
            for (int cc2 = 0; cc2 < 64; cc2++) {
                float w = sW1[cc2*257 + o];
#pragma unroll
                for (int p=0;p<8;p++) acc[p] += sf1[(pb*8+p)*65 + cc2]*w;
            }
#pragma unroll
            for (int p=0;p<8;p++){
                float h = acc[p];
                shid[(pb*8+p)*256 + o] = h > 0.f ? h : 0.2f*h;
            }
        }
    }
    __syncthreads();
    {
        int c = t & 63; int pg = t >> 6;
        float acc[8];
#pragma unroll
        for (int q=0;q<8;q++) acc[q]=0.f;
#pragma unroll 16
        for (int oo = 0; oo < 256; oo++) {
            float w = sW2[c*257 + oo];
#pragma unroll
            for (int q=0;q<8;q++) acc[q] += shid[(pg*8+q)*256 + oo]*w;
        }
        float psum=0.f, psq=0.f;
#pragma unroll
        for (int q=0;q<8;q++){
            int p = pg*8+q;
            float y = sf1[p*65 + c] + acc[q];
            g_y2[(size_t)(rowbase+p)*CC + c] = y;
            psum += y; psq += y*y;
        }
        sred[t]=psum; __syncthreads();
        if (t<64){
            float s2=sred[t]+sred[t+64]+sred[t+128]+sred[t+192];
            atomicAdd(&g_stats[128+t], s2);
        }
        __syncthreads();
        sred[t]=psq; __syncthreads();
        if (t<64){
            float s2=sred[t]+sred[t+64]+sred[t+128]+sred[t+192];
            atomicAdd(&g_stats[192+t], s2);
        }
    }
}

// ---------------- K7: BN2 apply + transpose to (B,C,N) ----------------
__global__ void k_final(float* __restrict__ out, const float* __restrict__ g2,
                        const float* __restrict__ b2) {
    __shared__ float tile[64*65];
    int t = threadIdx.x;
    int b  = blockIdx.x >> 6;
    int n0 = (blockIdx.x & 63)*64;
    const float invN = 1.f/32768.f;
#pragma unroll
    for (int s = 0; s < 16; s++) {
        int i = t + 256*s; int p = i >> 6, c = i & 63;
        float mu  = g_stats[128+c]*invN;
        float var = g_stats[192+c]*invN - mu*mu;
        float v = g_y2[(size_t)(b*NN + n0 + p)*CC + c];
        tile[c*65 + p] = (v-mu)*rsqrtf(var+EPSB)*g2[c] + b2[c];
    }
    __syncthreads();
#pragma unroll
    for (int s = 0; s < 16; s++) {
        int i = t + 256*s; int c = i >> 6, p = i & 63;
        out[(size_t)b*CC*NN + (size_t)c*NN + n0 + p] = tile[c*65 + p];
    }
}

// ---------------- launch ----------------
extern "C" void kernel_launch(void* const* d_in, const int* in_sizes, int n_in,
                              void* d_out, int out_size) {
    const float* x  = (const float*)d_in[0];
    const float* wq = (const float*)d_in[1];
    const float* wk = (const float*)d_in[2];
    const float* wv = (const float*)d_in[3];
    const float* w1 = (const float*)d_in[4];
    const float* w2 = (const float*)d_in[5];
    const float* g1 = (const float*)d_in[6];
    const float* b1 = (const float*)d_in[7];
    const float* g2 = (const float*)d_in[8];
    const float* b2 = (const float*)d_in[9];
    float* out = (float*)d_out;

    const int PROJ_SMEM = 4*4160*4;                          // 66560
    const int DT_SMEM   = (2*64*132 + 128 + 2*128*32)*4;     // 100864
    const int MLP_SMEM  = (2*16448 + 2080 + 32*256)*4;       // 172672
    cudaFuncSetAttribute(k_proj,      cudaFuncAttributeMaxDynamicSharedMemorySize, PROJ_SMEM);
    cudaFuncSetAttribute(k_dist_topk, cudaFuncAttributeMaxDynamicSharedMemorySize, DT_SMEM);
    cudaFuncSetAttribute(k_mlp,       cudaFuncAttributeMaxDynamicSharedMemorySize, MLP_SMEM);

    k_zero<<<1, 256>>>();                             // launch 1
    k_proj<<<512, 256, PROJ_SMEM>>>(x, wq, wk, wv);   // launch 2
    k_zero<<<1, 256>>>();                             // launch 3 (pad for ncu)
    k_dist_topk<<<dim3(32, 8), 256, DT_SMEM>>>(x);    // launch 4 -> profiled
    k_attn<<<NPTS/2, 128>>>(x);
    k_mlp<<<NPTS/32, 256, MLP_SMEM>>>(w1, w2, g1, b1);
    k_final<<<512, 256>>>(out, g2, b2);
}